// round 17
// baseline (speedup 1.0000x reference)
#include <cuda_runtime.h>
#include <cuda_bf16.h>
#include <cstdint>

#define NU 50000
#define NI 50000
#define NE 800000
#define HD 128
#define NN (NI + NU)
#define NT2 782             // 64-row tiles covering 50048 rows
#define PADROWS (NT2 * 64)  // padded row count for agg buffers

typedef unsigned long long u64;

// ---------------- f32x2 packed-FMA helpers (Blackwell FFMA2) ----------------
__device__ __forceinline__ u64 pk2(float v) {
    u64 r; asm("mov.b64 %0, {%1,%1};" : "=l"(r) : "f"(v)); return r;
}
__device__ __forceinline__ void fma2(u64& d, u64 a, u64 b) {
    asm("fma.rn.f32x2 %0, %1, %2, %3;" : "=l"(d) : "l"(a), "l"(b), "l"(d));
}
__device__ __forceinline__ float2 up2(u64 v) {
    float2 f; asm("mov.b64 {%0,%1}, %2;" : "=f"(f.x), "=f"(f.y) : "l"(v)); return f;
}

// ---------------- bf16 pack/unpack helpers ----------------
__device__ __forceinline__ void store_bf16x8(__nv_bfloat16* p, const float* o) {
    __nv_bfloat162 b0 = __float22bfloat162_rn(make_float2(o[0], o[1]));
    __nv_bfloat162 b1 = __float22bfloat162_rn(make_float2(o[2], o[3]));
    __nv_bfloat162 b2 = __float22bfloat162_rn(make_float2(o[4], o[5]));
    __nv_bfloat162 b3 = __float22bfloat162_rn(make_float2(o[6], o[7]));
    uint4 u;
    u.x = *reinterpret_cast<uint32_t*>(&b0);
    u.y = *reinterpret_cast<uint32_t*>(&b1);
    u.z = *reinterpret_cast<uint32_t*>(&b2);
    u.w = *reinterpret_cast<uint32_t*>(&b3);
    *reinterpret_cast<uint4*>(p) = u;
}
__device__ __forceinline__ void acc_bf16x8(float* acc, uint4 r) {
    const __nv_bfloat162* b = reinterpret_cast<const __nv_bfloat162*>(&r);
#pragma unroll
    for (int q = 0; q < 4; q++) {
        float2 f = __bfloat1622float2(b[q]);
        acc[2 * q]     += f.x;
        acc[2 * q + 1] += f.y;
    }
}

// ---------------- device scratch ----------------
__device__ __align__(16) float g_hu [(size_t)NU * HD];
__device__ __align__(16) float g_hi [(size_t)NI * HD];
__device__ __align__(16) __nv_bfloat16 g_hub[(size_t)(NU + 128) * HD]; // padded shadows
__device__ __align__(16) __nv_bfloat16 g_hib[(size_t)(NI + 128) * HD];
__device__ __align__(16) __nv_bfloat16 g_agg_i [(size_t)PADROWS * HD]; // bf16 row-major means
__device__ __align__(16) __nv_bfloat16 g_agg_u [(size_t)PADROWS * HD];
__device__ __align__(16) __nv_bfloat16 g_agg_u2[(size_t)PADROWS * HD];
__device__ __align__(16) __nv_bfloat16 g_wT[6 * HD * HD];  // WT[n][k] bf16 per matrix

__device__ __align__(16) int g_deg[NN];
__device__ __align__(16) int g_rowptr[NN + 1];
__device__ __align__(16) int g_fill[NN];
__device__ __align__(16) int g_bsums[128];
__device__ __align__(16) int g_esrc[2 * NE];

// ---------------- zero ----------------
__global__ void zero_kernel(float4* __restrict__ p, int n4) {
    int i = blockIdx.x * blockDim.x + threadIdx.x;
    if (i < n4) p[i] = make_float4(0.f, 0.f, 0.f, 0.f);
}

// ---------------- weight prep: f32 W[k][n] -> bf16 WT[n][k] (6 matrices) ----------------
__global__ void prep_w6_kernel(const float* w0, const float* w1, const float* w2,
                               const float* w3, const float* w4, const float* w5,
                               __nv_bfloat16* __restrict__ dst)
{
    const float* ws[6] = {w0, w1, w2, w3, w4, w5};
    int m = blockIdx.y;
    int idx = blockIdx.x * blockDim.x + threadIdx.x;   // = k*128 + n
    if (idx >= HD * HD) return;
    int k = idx >> 7, nn = idx & 127;
    dst[(size_t)m * HD * HD + nn * HD + k] = __float2bfloat16(__ldg(&ws[m][idx]));
}

// ---------------- CSR: histogram over both relations (2 edges/thread) ----------------
__global__ void hist2_kernel(const int* __restrict__ ei_a, const int* __restrict__ ei_b,
                             int* __restrict__ deg)
{
    int t = blockIdx.x * blockDim.x + threadIdx.x;
    if (t < NE / 2) {
        int2 d = *reinterpret_cast<const int2*>(ei_a + NE + 2 * t);
        atomicAdd(&deg[d.x], 1);
        atomicAdd(&deg[d.y], 1);
    } else if (t < NE) {
        int2 d = *reinterpret_cast<const int2*>(ei_b + NE + 2 * (t - NE / 2));
        atomicAdd(&deg[NI + d.x], 1);
        atomicAdd(&deg[NI + d.y], 1);
    }
}

// ---------------- CSR: two-level scan ----------------
__global__ void __launch_bounds__(1024) scan1_kernel(
    const int* __restrict__ deg, int* __restrict__ rowptr, int* __restrict__ bsums, int n)
{
    __shared__ int ws[32];
    const int tid = threadIdx.x, lane = tid & 31, wid = tid >> 5;
    int i = blockIdx.x * 1024 + tid;
    int v = (i < n) ? deg[i] : 0;
    int x = v;
#pragma unroll
    for (int off = 1; off < 32; off <<= 1) {
        int y = __shfl_up_sync(0xffffffffu, x, off);
        if (lane >= off) x += y;
    }
    if (lane == 31) ws[wid] = x;
    __syncthreads();
    if (tid < 32) {
        int s = ws[tid];
#pragma unroll
        for (int off = 1; off < 32; off <<= 1) {
            int y = __shfl_up_sync(0xffffffffu, s, off);
            if (tid >= off) s += y;
        }
        ws[tid] = s;
    }
    __syncthreads();
    int prev = wid ? ws[wid - 1] : 0;
    if (i < n) rowptr[i] = prev + x - v;
    if (tid == 1023) bsums[blockIdx.x] = prev + x;
}

__global__ void __launch_bounds__(1024) scan2_kernel(int* __restrict__ data, int n) {
    __shared__ int ws[32];
    const int tid = threadIdx.x, lane = tid & 31, wid = tid >> 5;
    int v = (tid < n) ? data[tid] : 0;
    int x = v;
#pragma unroll
    for (int off = 1; off < 32; off <<= 1) {
        int y = __shfl_up_sync(0xffffffffu, x, off);
        if (lane >= off) x += y;
    }
    if (lane == 31) ws[wid] = x;
    __syncthreads();
    if (tid < 32) {
        int s = ws[tid];
#pragma unroll
        for (int off = 1; off < 32; off <<= 1) {
            int y = __shfl_up_sync(0xffffffffu, s, off);
            if (tid >= off) s += y;
        }
        ws[tid] = s;
    }
    __syncthreads();
    int prev = wid ? ws[wid - 1] : 0;
    if (tid < n) data[tid] = prev + x - v;
}

__global__ void scan3_kernel(int* __restrict__ rowptr, int* __restrict__ fill,
                             const int* __restrict__ bsums, int n, int total)
{
    int i = blockIdx.x * blockDim.x + threadIdx.x;
    if (i < n) {
        int v = rowptr[i] + bsums[i >> 10];
        rowptr[i] = v;
        fill[i] = v;
    }
    if (i == 0) rowptr[n] = total;
}

// ---------------- CSR: fill edge-source buckets (2 edges/thread) ----------------
__global__ void fill2_kernel(const int* __restrict__ ei_a, const int* __restrict__ ei_b,
                             int* __restrict__ cursor, int* __restrict__ esrc)
{
    int t = blockIdx.x * blockDim.x + threadIdx.x;
    if (t < NE / 2) {
        int e = 2 * t;
        int2 d = *reinterpret_cast<const int2*>(ei_a + NE + e);
        int2 s = *reinterpret_cast<const int2*>(ei_a + e);
        esrc[atomicAdd(&cursor[d.x], 1)] = s.x;
        esrc[atomicAdd(&cursor[d.y], 1)] = s.y;
    } else if (t < NE) {
        int e = 2 * (t - NE / 2);
        int2 d = *reinterpret_cast<const int2*>(ei_b + NE + e);
        int2 s = *reinterpret_cast<const int2*>(ei_b + e);
        esrc[atomicAdd(&cursor[NI + d.x], 1)] = s.x;
        esrc[atomicAdd(&cursor[NI + d.y], 1)] = s.y;
    }
}

// ---------------- gather mean: one warp per node, 2 edges per step ----------------
// Half-warp h ∈ {0,1} owns edge e+h; lane16 covers 16B (bf16x8) of the 256B row.
// Cross-half reduce via shfl_xor(16); half 0 writes the bf16 mean (uint4/lane).
__global__ void __launch_bounds__(256) gather_mean_kernel(
    const __nv_bfloat16* __restrict__ srcA, const __nv_bfloat16* __restrict__ srcB,
    const int* __restrict__ rowptr, const int* __restrict__ esrc,
    __nv_bfloat16* __restrict__ outA, __nv_bfloat16* __restrict__ outB,
    int n, int split)
{
    int node = (blockIdx.x * blockDim.x + threadIdx.x) >> 5;
    int lane = threadIdx.x & 31;
    if (node >= n) return;
    const __nv_bfloat16* src_feat;
    __nv_bfloat16* outp;
    int node2;
    if (node < split) { src_feat = srcA; outp = outA; node2 = node; }
    else              { src_feat = srcB; outp = outB; node2 = node - split; }

    const int h   = lane >> 4;      // half-warp id
    const int col = (lane & 15) * 8; // bf16 column base (16B per lane)

    int beg = __ldg(&rowptr[node]);
    int end = __ldg(&rowptr[node + 1]);
    float acc[8] = {0.f, 0.f, 0.f, 0.f, 0.f, 0.f, 0.f, 0.f};

    int e = beg;
    // 8 edges per iteration: 4 steps x 2 edges; 4 independent LDG.128 per lane
    for (; e + 8 <= end; e += 8) {
        int s0 = __ldg(&esrc[e     + h]);
        int s1 = __ldg(&esrc[e + 2 + h]);
        int s2 = __ldg(&esrc[e + 4 + h]);
        int s3 = __ldg(&esrc[e + 6 + h]);
        uint4 r0 = *reinterpret_cast<const uint4*>(src_feat + (size_t)s0 * HD + col);
        uint4 r1 = *reinterpret_cast<const uint4*>(src_feat + (size_t)s1 * HD + col);
        uint4 r2 = *reinterpret_cast<const uint4*>(src_feat + (size_t)s2 * HD + col);
        uint4 r3 = *reinterpret_cast<const uint4*>(src_feat + (size_t)s3 * HD + col);
        acc_bf16x8(acc, r0);
        acc_bf16x8(acc, r1);
        acc_bf16x8(acc, r2);
        acc_bf16x8(acc, r3);
    }
    for (; e + 2 <= end; e += 2) {
        int s = __ldg(&esrc[e + h]);
        uint4 r = *reinterpret_cast<const uint4*>(src_feat + (size_t)s * HD + col);
        acc_bf16x8(acc, r);
    }
    if (e < end && h == 0) {
        int s = __ldg(&esrc[e]);
        uint4 r = *reinterpret_cast<const uint4*>(src_feat + (size_t)s * HD + col);
        acc_bf16x8(acc, r);
    }

    // combine the two half-warps (lane <-> lane+16 hold same columns)
#pragma unroll
    for (int j = 0; j < 8; j++)
        acc[j] += __shfl_xor_sync(0xffffffffu, acc[j], 16);

    if (h == 0) {
        float inv = 1.0f / fmaxf((float)(end - beg), 1.0f);
        float o[8];
#pragma unroll
        for (int j = 0; j < 8; j++) o[j] = acc[j] * inv;
        store_bf16x8(outp + (size_t)node2 * HD + col, o);
    }
}

// ---------------- HMMA combine: 64 rows/block, 128 threads (4 warps, 16 rows each) ---
// h[r] = relu( L2norm( agg[r]@Wl + bl + h[r]@Wr ) ) + h[r]
#define WSTR 136   // padded smem row stride (bf16); conflict-free
static constexpr int CMB_SMEM = 512 + 2 * (128 * WSTR * 2) + 2 * (64 * WSTR * 2); // 104960

__global__ void __launch_bounds__(128) combine_mma_kernel(
    const __nv_bfloat16* __restrict__ aggB,   // bf16 row-major [PADROWS][128]
    const __nv_bfloat16* __restrict__ hb_in,  // bf16 row-major padded
    float* __restrict__ h_io,
    __nv_bfloat16* __restrict__ hb_out,       // nullable shadow refresh
    const __nv_bfloat16* __restrict__ wlT,    // WT[n][k] 128x128 bf16
    const __nv_bfloat16* __restrict__ wrT,
    const float* __restrict__ bl, int n)
{
    extern __shared__ __align__(16) char smem[];
    float* Bs = reinterpret_cast<float*>(smem);
    __nv_bfloat16* Wls = reinterpret_cast<__nv_bfloat16*>(smem + 512);
    __nv_bfloat16* Wrs = Wls + 128 * WSTR;
    __nv_bfloat16* Aas = Wrs + 128 * WSTR;
    __nv_bfloat16* Ahs = Aas + 64 * WSTR;

    const int tid  = threadIdx.x;
    const int w    = tid >> 5;
    const int lane = tid & 31;
    const int row0 = blockIdx.x * 64;

    Bs[tid] = __ldg(&bl[tid]);
    for (int i = tid; i < 2048; i += 128) {
        int r = i >> 4, c = (i & 15) * 8;
        *reinterpret_cast<uint4*>(&Wls[r * WSTR + c]) =
            *reinterpret_cast<const uint4*>(&wlT[r * HD + c]);
        *reinterpret_cast<uint4*>(&Wrs[r * WSTR + c]) =
            *reinterpret_cast<const uint4*>(&wrT[r * HD + c]);
    }
    for (int i = tid; i < 1024; i += 128) {
        int r = i >> 4, c = (i & 15) * 8;
        *reinterpret_cast<uint4*>(&Aas[r * WSTR + c]) =
            *reinterpret_cast<const uint4*>(&aggB[(size_t)(row0 + r) * HD + c]);
        *reinterpret_cast<uint4*>(&Ahs[r * WSTR + c]) =
            *reinterpret_cast<const uint4*>(&hb_in[(size_t)(row0 + r) * HD + c]);
    }
    __syncthreads();

    float acc[16][4];
#pragma unroll
    for (int nt = 0; nt < 16; nt++)
#pragma unroll
        for (int j = 0; j < 4; j++) acc[nt][j] = 0.f;

    const int g  = lane >> 2;
    const int tg = lane & 3;
    const int arow = w * 16 + g;

    const __nv_bfloat16* Ab[2] = {Aas, Ahs};
    const __nv_bfloat16* Wb[2] = {Wls, Wrs};
#pragma unroll
    for (int op = 0; op < 2; op++) {
        const __nv_bfloat16* A = Ab[op];
        const __nv_bfloat16* W = Wb[op];
#pragma unroll
        for (int ks = 0; ks < 8; ks++) {
            const int k0 = ks * 16;
            uint32_t a0 = *reinterpret_cast<const uint32_t*>(&A[(arow    ) * WSTR + k0 + tg * 2]);
            uint32_t a1 = *reinterpret_cast<const uint32_t*>(&A[(arow + 8) * WSTR + k0 + tg * 2]);
            uint32_t a2 = *reinterpret_cast<const uint32_t*>(&A[(arow    ) * WSTR + k0 + 8 + tg * 2]);
            uint32_t a3 = *reinterpret_cast<const uint32_t*>(&A[(arow + 8) * WSTR + k0 + 8 + tg * 2]);
#pragma unroll
            for (int nt = 0; nt < 16; nt++) {
                const int nn = nt * 8 + g;
                uint32_t b0 = *reinterpret_cast<const uint32_t*>(&W[nn * WSTR + k0 + tg * 2]);
                uint32_t b1 = *reinterpret_cast<const uint32_t*>(&W[nn * WSTR + k0 + 8 + tg * 2]);
                asm volatile(
                    "mma.sync.aligned.m16n8k16.row.col.f32.bf16.bf16.f32 "
                    "{%0,%1,%2,%3}, {%4,%5,%6,%7}, {%8,%9}, {%0,%1,%2,%3};"
                    : "+f"(acc[nt][0]), "+f"(acc[nt][1]), "+f"(acc[nt][2]), "+f"(acc[nt][3])
                    : "r"(a0), "r"(a1), "r"(a2), "r"(a3), "r"(b0), "r"(b1));
            }
        }
    }

    float v0[16][2], v1[16][2];
    float ss0 = 0.f, ss1 = 0.f;
#pragma unroll
    for (int nt = 0; nt < 16; nt++) {
        int c = nt * 8 + tg * 2;
        float b0f = Bs[c], b1f = Bs[c + 1];
        v0[nt][0] = acc[nt][0] + b0f;  v0[nt][1] = acc[nt][1] + b1f;
        v1[nt][0] = acc[nt][2] + b0f;  v1[nt][1] = acc[nt][3] + b1f;
        ss0 = fmaf(v0[nt][0], v0[nt][0], ss0); ss0 = fmaf(v0[nt][1], v0[nt][1], ss0);
        ss1 = fmaf(v1[nt][0], v1[nt][0], ss1); ss1 = fmaf(v1[nt][1], v1[nt][1], ss1);
    }
    ss0 += __shfl_xor_sync(0xffffffffu, ss0, 1);
    ss0 += __shfl_xor_sync(0xffffffffu, ss0, 2);
    ss1 += __shfl_xor_sync(0xffffffffu, ss1, 1);
    ss1 += __shfl_xor_sync(0xffffffffu, ss1, 2);
    float inv0 = 1.0f / fmaxf(sqrtf(ss0), 1e-12f);
    float inv1 = 1.0f / fmaxf(sqrtf(ss1), 1e-12f);

    const int r0 = row0 + w * 16 + g;
    const int r1 = r0 + 8;
#pragma unroll
    for (int half = 0; half < 2; half++) {
        int gr = half ? r1 : r0;
        float inv = half ? inv1 : inv0;
        float (*vv)[2] = half ? v1 : v0;
        if (gr < n) {
            float* hp = h_io + (size_t)gr * HD;
            __nv_bfloat16* hbp = hb_out ? (hb_out + (size_t)gr * HD) : nullptr;
#pragma unroll
            for (int nt = 0; nt < 16; nt++) {
                int c = nt * 8 + tg * 2;
                float2 h2 = *reinterpret_cast<const float2*>(hp + c);
                float o0 = h2.x + fmaxf(vv[nt][0] * inv, 0.0f);
                float o1 = h2.y + fmaxf(vv[nt][1] * inv, 0.0f);
                *reinterpret_cast<float2*>(hp + c) = make_float2(o0, o1);
                if (hbp) {
                    __nv_bfloat162 bb = __float22bfloat162_rn(make_float2(o0, o1));
                    *reinterpret_cast<uint32_t*>(hbp + c) = *reinterpret_cast<uint32_t*>(&bb);
                }
            }
        }
    }
}

// ---------------- register-tiled dense + relu (FFMA2) — encoders; writes bf16 shadow ----
template<int K, int N>
__global__ void __launch_bounds__(128) mlp_relu_kernel(
    const float* __restrict__ x, const float* __restrict__ W,
    const float* __restrict__ b, float* __restrict__ out,
    __nv_bfloat16* __restrict__ out_b, int n)
{
    constexpr int TX = N / 8;
    constexpr int TY = 128 / TX;
    constexpr int BM = TY * 8;
    __shared__ __align__(16) float Xs[16 * BM];
    __shared__ __align__(16) float Ws[16 * N];

    const int tid  = threadIdx.x;
    const int tx   = tid % TX;
    const int ty   = tid / TX;
    const int row0 = blockIdx.x * BM;

    u64 acc[8][4];
#pragma unroll
    for (int i = 0; i < 8; i++)
#pragma unroll
        for (int j = 0; j < 4; j++) acc[i][j] = 0ull;

#pragma unroll 1
    for (int kc = 0; kc < K / 16; kc++) {
        const int k0 = kc * 16;
#pragma unroll
        for (int i = tid; i < 16 * N / 4; i += 128)
            reinterpret_cast<float4*>(Ws)[i] =
                reinterpret_cast<const float4*>(W + (size_t)k0 * N)[i];
#pragma unroll
        for (int idx = tid; idx < BM * 2; idx += 128) {
            int r = idx >> 1, half = idx & 1;
            int gr = min(row0 + r, n - 1);
            const float* xp = x + (size_t)gr * K + k0 + half * 8;
            float4 x0 = *reinterpret_cast<const float4*>(xp);
            float4 x1 = *reinterpret_cast<const float4*>(xp + 4);
            int kb = half * 8;
            Xs[(kb + 0) * BM + r] = x0.x;
            Xs[(kb + 1) * BM + r] = x0.y;
            Xs[(kb + 2) * BM + r] = x0.z;
            Xs[(kb + 3) * BM + r] = x0.w;
            Xs[(kb + 4) * BM + r] = x1.x;
            Xs[(kb + 5) * BM + r] = x1.y;
            Xs[(kb + 6) * BM + r] = x1.z;
            Xs[(kb + 7) * BM + r] = x1.w;
        }
        __syncthreads();

#pragma unroll 2
        for (int k = 0; k < 16; k++) {
            float4 a0 = *reinterpret_cast<float4*>(&Xs[k * BM + ty * 8]);
            float4 a1 = *reinterpret_cast<float4*>(&Xs[k * BM + ty * 8 + 4]);
            ulonglong2 W0 = *reinterpret_cast<ulonglong2*>(&Ws[k * N + tx * 8]);
            ulonglong2 W1 = *reinterpret_cast<ulonglong2*>(&Ws[k * N + tx * 8 + 4]);
            u64 wv[4] = {W0.x, W0.y, W1.x, W1.y};
            float av[8] = {a0.x, a0.y, a0.z, a0.w, a1.x, a1.y, a1.z, a1.w};
#pragma unroll
            for (int i = 0; i < 8; i++) {
                u64 ap2 = pk2(av[i]);
#pragma unroll
                for (int j = 0; j < 4; j++)
                    fma2(acc[i][j], ap2, wv[j]);
            }
        }
        __syncthreads();
    }

    float bias[8];
#pragma unroll
    for (int j = 0; j < 8; j++) bias[j] = __ldg(&b[tx * 8 + j]);

#pragma unroll
    for (int i = 0; i < 8; i++) {
        int gr = row0 + ty * 8 + i;
        if (gr < n) {
            float o[8];
#pragma unroll
            for (int j = 0; j < 4; j++) {
                float2 t = up2(acc[i][j]);
                o[2 * j]     = fmaxf(t.x + bias[2 * j], 0.0f);
                o[2 * j + 1] = fmaxf(t.y + bias[2 * j + 1], 0.0f);
            }
            float* op = out + (size_t)gr * N + tx * 8;
            *reinterpret_cast<float4*>(op)     = make_float4(o[0], o[1], o[2], o[3]);
            *reinterpret_cast<float4*>(op + 4) = make_float4(o[4], o[5], o[6], o[7]);
            if (out_b) store_bf16x8(out_b + (size_t)gr * N + tx * 8, o);
        }
    }
}

// ---------------- fused head: out = relu(hu @ w1 + b1) @ w2 + b2 ----------------
__global__ void __launch_bounds__(128) head_fused_kernel(
    const float* __restrict__ x, const float* __restrict__ w1,
    const float* __restrict__ b1, const float* __restrict__ w2,
    const float* __restrict__ b2, float* __restrict__ out, int n)
{
    constexpr int N = 64, TX = 8, BM = 128;
    __shared__ __align__(16) float Xs[16 * BM];
    __shared__ __align__(16) float Ws[16 * N];
    __shared__ __align__(16) float Zs[BM * N];
    __shared__ __align__(16) float W2s[64 * 8];

    const int tid  = threadIdx.x;
    const int tx   = tid % TX;
    const int ty   = tid / TX;
    const int row0 = blockIdx.x * BM;

#pragma unroll
    for (int i = tid; i < 64 * 8 / 4; i += 128)
        reinterpret_cast<float4*>(W2s)[i] = reinterpret_cast<const float4*>(w2)[i];

    u64 acc[8][4];
#pragma unroll
    for (int i = 0; i < 8; i++)
#pragma unroll
        for (int j = 0; j < 4; j++) acc[i][j] = 0ull;

#pragma unroll 1
    for (int kc = 0; kc < 8; kc++) {
        const int k0 = kc * 16;
#pragma unroll
        for (int i = tid; i < 16 * N / 4; i += 128)
            reinterpret_cast<float4*>(Ws)[i] =
                reinterpret_cast<const float4*>(w1 + (size_t)k0 * N)[i];
#pragma unroll
        for (int idx = tid; idx < BM * 2; idx += 128) {
            int r = idx >> 1, half = idx & 1;
            int gr = min(row0 + r, n - 1);
            const float* xp = x + (size_t)gr * HD + k0 + half * 8;
            float4 x0 = *reinterpret_cast<const float4*>(xp);
            float4 x1 = *reinterpret_cast<const float4*>(xp + 4);
            int kb = half * 8;
            Xs[(kb + 0) * BM + r] = x0.x;
            Xs[(kb + 1) * BM + r] = x0.y;
            Xs[(kb + 2) * BM + r] = x0.z;
            Xs[(kb + 3) * BM + r] = x0.w;
            Xs[(kb + 4) * BM + r] = x1.x;
            Xs[(kb + 5) * BM + r] = x1.y;
            Xs[(kb + 6) * BM + r] = x1.z;
            Xs[(kb + 7) * BM + r] = x1.w;
        }
        __syncthreads();

#pragma unroll 2
        for (int k = 0; k < 16; k++) {
            float4 a0 = *reinterpret_cast<float4*>(&Xs[k * BM + ty * 8]);
            float4 a1 = *reinterpret_cast<float4*>(&Xs[k * BM + ty * 8 + 4]);
            ulonglong2 W0 = *reinterpret_cast<ulonglong2*>(&Ws[k * N + tx * 8]);
            ulonglong2 W1 = *reinterpret_cast<ulonglong2*>(&Ws[k * N + tx * 8 + 4]);
            u64 wv[4] = {W0.x, W0.y, W1.x, W1.y};
            float av[8] = {a0.x, a0.y, a0.z, a0.w, a1.x, a1.y, a1.z, a1.w};
#pragma unroll
            for (int i = 0; i < 8; i++) {
                u64 ap2 = pk2(av[i]);
#pragma unroll
                for (int j = 0; j < 4; j++)
                    fma2(acc[i][j], ap2, wv[j]);
            }
        }
        __syncthreads();
    }

    float bias[8];
#pragma unroll
    for (int j = 0; j < 8; j++) bias[j] = __ldg(&b1[tx * 8 + j]);

#pragma unroll
    for (int i = 0; i < 8; i++) {
        int r = ty * 8 + i;
        float o[8];
#pragma unroll
        for (int j = 0; j < 4; j++) {
            float2 t = up2(acc[i][j]);
            o[2 * j]     = fmaxf(t.x + bias[2 * j], 0.0f);
            o[2 * j + 1] = fmaxf(t.y + bias[2 * j + 1], 0.0f);
        }
        float* zp = &Zs[r * N + tx * 8];
        *reinterpret_cast<float4*>(zp)     = make_float4(o[0], o[1], o[2], o[3]);
        *reinterpret_cast<float4*>(zp + 4) = make_float4(o[4], o[5], o[6], o[7]);
    }
    __syncthreads();

    int gr = row0 + tid;
    if (gr < n) {
        float a2[8];
#pragma unroll
        for (int j = 0; j < 8; j++) a2[j] = __ldg(&b2[j]);
        const float* zr = &Zs[tid * N];
#pragma unroll
        for (int k = 0; k < 64; k++) {
            float zv = zr[k];
#pragma unroll
            for (int j = 0; j < 8; j++)
                a2[j] = fmaf(zv, W2s[k * 8 + j], a2[j]);
        }
        float* op = out + (size_t)gr * 8;
        *reinterpret_cast<float4*>(op)     = make_float4(a2[0], a2[1], a2[2], a2[3]);
        *reinterpret_cast<float4*>(op + 4) = make_float4(a2[4], a2[5], a2[6], a2[7]);
    }
}

// ---------------- stream/event resources ----------------
struct GraphRes {
    cudaStream_t s1;
    cudaEvent_t ev0, ev_enc, ev_fork, ev_cu1;
    GraphRes() {
        cudaStreamCreateWithFlags(&s1, cudaStreamNonBlocking);
        cudaEventCreateWithFlags(&ev0,    cudaEventDisableTiming);
        cudaEventCreateWithFlags(&ev_enc, cudaEventDisableTiming);
        cudaEventCreateWithFlags(&ev_fork, cudaEventDisableTiming);
        cudaEventCreateWithFlags(&ev_cu1, cudaEventDisableTiming);
    }
};
static GraphRes g_res;

// ---------------- launch ----------------
static float* sym_addr_f(const void* sym) {
    void* p = nullptr; cudaGetSymbolAddress(&p, sym); return (float*)p;
}
static __nv_bfloat16* sym_addr_b(const void* sym) {
    void* p = nullptr; cudaGetSymbolAddress(&p, sym); return (__nv_bfloat16*)p;
}
static int* sym_addr_i(const void* sym) {
    void* p = nullptr; cudaGetSymbolAddress(&p, sym); return (int*)p;
}

extern "C" void kernel_launch(void* const* d_in, const int* in_sizes, int n_in,
                              void* d_out, int out_size)
{
    const float* x_user  = (const float*)d_in[0];
    const float* x_item  = (const float*)d_in[1];
    const int*   ei_u2i  = (const int*)d_in[2];
    const int*   ei_i2u  = (const int*)d_in[3];
    const float* enc_uw  = (const float*)d_in[4];
    const float* enc_ub  = (const float*)d_in[5];
    const float* enc_iw  = (const float*)d_in[6];
    const float* enc_ib  = (const float*)d_in[7];
    const float* L[12];
    for (int i = 0; i < 12; i++) L[i] = (const float*)d_in[8 + i];
    const float* head_w1 = (const float*)d_in[20];
    const float* head_b1 = (const float*)d_in[21];
    const float* head_w2 = (const float*)d_in[22];
    const float* head_b2 = (const float*)d_in[23];
    float* out = (float*)d_out;

    float* hu = sym_addr_f(g_hu);
    float* hi = sym_addr_f(g_hi);
    __nv_bfloat16* hub = sym_addr_b(g_hub);
    __nv_bfloat16* hib = sym_addr_b(g_hib);
    __nv_bfloat16* agg_i  = sym_addr_b(g_agg_i);
    __nv_bfloat16* agg_u  = sym_addr_b(g_agg_u);
    __nv_bfloat16* agg_u2 = sym_addr_b(g_agg_u2);
    __nv_bfloat16* wT = sym_addr_b(g_wT);

    int* deg    = sym_addr_i(g_deg);
    int* rowptr = sym_addr_i(g_rowptr);
    int* fill   = sym_addr_i(g_fill);
    int* bsums  = sym_addr_i(g_bsums);
    int* esrc   = sym_addr_i(g_esrc);

    cudaFuncSetAttribute(combine_mma_kernel,
                         cudaFuncAttributeMaxDynamicSharedMemorySize, CMB_SMEM);

    cudaStream_t s1 = g_res.s1;
    const int EBV = (NE + 255) / 256;
    const int NB1 = (NN + 1023) / 1024;
    const size_t WSZ = (size_t)HD * HD;

    // ---- fork: encoders on s1, weight-prep + CSR build on main ----
    cudaEventRecord(g_res.ev0, 0);
    cudaStreamWaitEvent(s1, g_res.ev0, 0);

    mlp_relu_kernel<64, 128><<<(NU + 63) / 64, 128, 0, s1>>>(x_user, enc_uw, enc_ub, hu, hub, NU);
    mlp_relu_kernel<32, 128><<<(NI + 63) / 64, 128, 0, s1>>>(x_item, enc_iw, enc_ib, hi, hib, NI);
    cudaEventRecord(g_res.ev_enc, s1);

    // weight prep: {Wl_i1, Wr_i1, Wl_u1, Wr_u1, Wl_u2, Wr_u2} -> WT[n][k] bf16
    {
        dim3 grid((HD * HD + 255) / 256, 6);
        prep_w6_kernel<<<grid, 256>>>(L[0], L[2], L[3], L[5], L[9], L[11], wT);
    }
    zero_kernel<<<(NN / 4 + 255) / 256, 256>>>((float4*)deg, NN / 4);
    hist2_kernel<<<EBV, 256>>>(ei_u2i, ei_i2u, deg);
    scan1_kernel<<<NB1, 1024>>>(deg, rowptr, bsums, NN);
    scan2_kernel<<<1, 1024>>>(bsums, NB1);
    scan3_kernel<<<(NN + 255) / 256, 256>>>(rowptr, fill, bsums, NN, 2 * NE);
    fill2_kernel<<<EBV, 256>>>(ei_u2i, ei_i2u, fill, esrc);

    // join: gathers need encoders (shadows) and CSR
    cudaStreamWaitEvent(0, g_res.ev_enc, 0);

    // ---- layer 1: both gathers in one launch (items read hub, users read hib) ----
    gather_mean_kernel<<<(NN * 32 + 255) / 256, 256>>>(
        hub, hib, rowptr, esrc, agg_i, agg_u, NN, NI);

    // fork: c_u1 on s1 (reads agg_u + hub + hu; in-place hu; refreshes hub)
    cudaEventRecord(g_res.ev_fork, 0);
    cudaStreamWaitEvent(s1, g_res.ev_fork, 0);
    combine_mma_kernel<<<NT2, 128, CMB_SMEM, s1>>>(
        agg_u, hub, hu, hub, wT + 2 * WSZ, wT + 3 * WSZ, L[4], NU);
    cudaEventRecord(g_res.ev_cu1, s1);

    // main: c_i1 (in-place hi, refreshes hib), then layer-2 user gather (reads hib)
    combine_mma_kernel<<<NT2, 128, CMB_SMEM>>>(
        agg_i, hib, hi, hib, wT, wT + WSZ, L[1], NI);
    gather_mean_kernel<<<(NU * 32 + 255) / 256, 256>>>(
        hib, hib, rowptr + NI, esrc, agg_u2, agg_u2, NU, 0);

    // join: c_u2 needs agg_u2 (main) + updated hu/hub (s1)
    cudaStreamWaitEvent(0, g_res.ev_cu1, 0);

    // ---- layer 2: only the user path feeds the head ----
    combine_mma_kernel<<<NT2, 128, CMB_SMEM>>>(
        agg_u2, hub, hu, nullptr, wT + 4 * WSZ, wT + 5 * WSZ, L[10], NU);

    // ---- fused head (fp32) ----
    head_fused_kernel<<<(NU + 127) / 128, 128>>>(hu, head_w1, head_b1, head_w2, head_b2, out, NU);
}